// round 11
// baseline (speedup 1.0000x reference)
#include <cuda_runtime.h>
#include <cuda_bf16.h>

#define NMASKS 128
#define W      1024
#define TILE_ROWS 62
#define TILES_PER_MASK 17                    // 16 x 62 rows + 1 x 32 rows
#define NTILES (NMASKS * TILES_PER_MASK)     // 2176
#define NPBLK  740                           // 148 SMs x 5 resident blocks
#define HALO_MAX 64                          // 62 + 2 -> 8 pack iters/warp
#define STRIDE 35                            // gcd(35,32)=1 -> conflict-free
#define NSTAGE 8                             // staged halo rows of next tile

__device__ unsigned g_mA[NMASKS];            // zero-init; reset by last block
__device__ unsigned g_mC[NMASKS];
__device__ unsigned g_mP[NMASKS];
__device__ unsigned g_ticket = 0;            // reset by last block each launch
__device__ unsigned g_done = 0;              // atomicInc wrap -> self-resetting

__device__ __forceinline__ void csa(unsigned a, unsigned b, unsigned c,
                                    unsigned &s, unsigned &cy) {
    unsigned t = a ^ b;
    s  = t ^ c;
    cy = (a & b) | (t & c);
}

__device__ __forceinline__ unsigned smem_u32(const void* p) {
    return (unsigned)__cvta_generic_to_shared(p);
}

__global__ __launch_bounds__(256, 5)
void prior_kernel(const float* __restrict__ masks, float* __restrict__ out) {
    // Interleaved-bitplane packed rows. Group g (128 cols) occupies slots
    // 1+4g..4+4g. Guard slots 0 / 33 / 34 stay zero.
    __shared__ unsigned srows[HALO_MAX][STRIDE];   // 9.24 KB
    __shared__ float    stage[NSTAGE][W];          // 32 KB: next tile's top halo
    __shared__ int sTick;
    __shared__ int is_last;

    const int tid  = threadIdx.x;
    const int lane = tid & 31;
    const int wp   = tid >> 5;               // 8 warps

    for (int j = tid; j < HALO_MAX; j += 256) {
        srows[j][0] = 0u; srows[j][33] = 0u; srows[j][34] = 0u;
    }

    // issue_staging(t): each thread cp.asyncs its 16B of each of the first
    // NSTAGE halo rows of tile t into stage[]. One commit group total.
    auto issue_staging = [&](int t) {
        int m  = t / TILES_PER_MASK;
        int ti = t - m * TILES_PER_MASK;
        int r0 = ti * TILE_ROWS;
        const char* gbase = (const char*)masks
                          + (size_t)m * (size_t)(W * W) * 4
                          + (size_t)(r0 - 1) * (W * 4) + tid * 16;
        #pragma unroll
        for (int j = 0; j < NSTAGE; j++) {
            int gr = r0 - 1 + j;                       // gr <= 999 always
            if (gr >= 0) {
                unsigned daddr = smem_u32(&stage[j][0]) + tid * 16;
                const char* sp = gbase + (size_t)j * (W * 4);
                asm volatile("cp.async.cg.shared.global [%0], [%1], 16;\n"
                             :: "r"(daddr), "l"(sp) : "memory");
            }
        }
        asm volatile("cp.async.commit_group;\n" ::: "memory");
    };

    // ---- prologue ----
    if (tid == 0) sTick = (int)atomicAdd(&g_ticket, 1u);
    __syncthreads();
    int t = sTick;
    if (t < NTILES) issue_staging(t);

    // ---- persistent loop ----
    while (t < NTILES) {
        asm volatile("cp.async.wait_group 0;\n" ::: "memory"); // staging arrived
        if (tid == 0) sTick = (int)atomicAdd(&g_ticket, 1u);
        __syncthreads();   // A: staging visible block-wide; sTick published

        const int mask = t / TILES_PER_MASK;
        const int tile = t - mask * TILES_PER_MASK;
        const int r0   = tile * TILE_ROWS;
        const int rows = (tile < 16) ? TILE_ROWS : (W - 16 * TILE_ROWS); // 62|32
        const int halo = rows + 2;
        const float4* __restrict__ base =
            (const float4*)(masks + (size_t)mask * (size_t)(W * W));

        // ---- pack: rows 0..7 from smem staging, rows 8+ via batched LDG ----
        for (int k = wp; k < halo; k += 8) {
            int gr = r0 - 1 + k;
            if ((unsigned)gr >= (unsigned)W) {
                srows[k][lane] = 0u;
            } else {
                float4 v[8];
                if (k < NSTAGE) {
                    const float4* __restrict__ sp = (const float4*)stage[k];
                    #pragma unroll
                    for (int it = 0; it < 8; it++) v[it] = sp[it * 32 + lane];
                } else {
                    const float4* __restrict__ rowp = base + (size_t)gr * (W / 4);
                    #pragma unroll
                    for (int it = 0; it < 8; it++) v[it] = rowp[it * 32 + lane];
                }
                #pragma unroll
                for (int it = 0; it < 8; it++) {
                    unsigned p0 = __ballot_sync(0xffffffffu, v[it].x > 0.0f);
                    unsigned p1 = __ballot_sync(0xffffffffu, v[it].y > 0.0f);
                    unsigned p2 = __ballot_sync(0xffffffffu, v[it].z > 0.0f);
                    unsigned p3 = __ballot_sync(0xffffffffu, v[it].w > 0.0f);
                    unsigned mine = (lane == 0) ? p0 : (lane == 1) ? p1
                                  : (lane == 2) ? p2 : p3;
                    if (lane < 4) srows[k][1 + 4 * it + lane] = mine;
                }
            }
        }
        __syncthreads();   // B: packed tile visible

        // ---- overlap: issue next tile's staging BEFORE compute ----
        const int t_next = sTick;
        if (t_next < NTILES) issue_staging(t_next);

        // ---- compute: rows x 8 groups tasks over 256 threads ----
        unsigned accA = 0, accC = 0, accP = 0;
        const int ntasks = rows * 8;         // 496 or 256
        #pragma unroll 1
        for (int base_t = 0; base_t < ntasks; base_t += 256) {
            int id = tid + base_t;
            if (id >= ntasks) break;
            int g  = id & 7;
            int r  = id >> 3;
            const unsigned* __restrict__ Tr = srows[r];
            const unsigned* __restrict__ Mr = srows[r + 1];
            const unsigned* __restrict__ Br = srows[r + 2];
            int s = 1 + 4 * g;

            unsigned T[4], M[4], B[4];
            #pragma unroll
            for (int k = 0; k < 4; k++) { T[k] = Tr[s+k]; M[k] = Mr[s+k]; B[k] = Br[s+k]; }
            unsigned Tp3 = Tr[s-1], Mp3 = Mr[s-1], Bp3 = Br[s-1];
            unsigned Tn0 = Tr[s+4], Mn0 = Mr[s+4], Bn0 = Br[s+4];

            unsigned TSL = (T[3] << 1) | (Tp3 >> 31), TSR = (T[0] >> 1) | (Tn0 << 31);
            unsigned MSL = (M[3] << 1) | (Mp3 >> 31), MSR = (M[0] >> 1) | (Mn0 << 31);
            unsigned BSL = (B[3] << 1) | (Bp3 >> 31), BSR = (B[0] >> 1) | (Bn0 << 31);

            #pragma unroll
            for (int k = 0; k < 4; k++) {
                unsigned tl = (k > 0) ? T[k-1] : TSL;
                unsigned ml = (k > 0) ? M[k-1] : MSL;
                unsigned bl = (k > 0) ? B[k-1] : BSL;
                unsigned tr = (k < 3) ? T[k+1] : TSR;
                unsigned mr = (k < 3) ? M[k+1] : MSR;
                unsigned br = (k < 3) ? B[k+1] : BSR;
                unsigned tt = T[k], bot = B[k], mid = M[k];

                unsigned s1, c1, s2, c2, s3, c3;
                csa(tl, tt, tr, s1, c1);
                csa(ml, mr, bl, s2, c2);
                csa(bot, br, s1, s3, c3);
                unsigned s4 = s2 ^ s3, c4 = s2 & s3;
                unsigned u1, v1;
                csa(c1, c2, c3, u1, v1);
                unsigned u2 = u1 ^ c4, v2 = u1 & c4;
                unsigned b0 = s4, b1 = u2, b2 = v1 ^ v2, b3 = v1 & v2;

                accA += __popc(mid);

                unsigned conn = __popc(b0 & mid) + 2u * __popc(b1 & mid)
                              + 4u * __popc(b2 & mid) + 8u * __popc(b3 & mid);
                unsigned tot  = __popc(b0) + 2u * __popc(b1)
                              + 4u * __popc(b2) + 8u * __popc(b3);
                unsigned perim = (tot - conn)
                               + 4u * __popc(b3 & mid)
                               + 2u * __popc(b2 & b1 & mid)
                               +      __popc(b2 & b0 & mid);

                accC += conn;
                accP += perim;
            }
        }

        // ---- per-tile reduction: warp reduce + 3 REDG per warp ----
        accA = __reduce_add_sync(0xffffffffu, accA);
        accC = __reduce_add_sync(0xffffffffu, accC);
        accP = __reduce_add_sync(0xffffffffu, accP);
        if (lane == 0) {
            atomicAdd(&g_mA[mask], accA);
            atomicAdd(&g_mC[mask], accC);
            atomicAdd(&g_mP[mask], accP);
        }
        t = t_next;
        // loop-top wait+barrier protect stage/srows before reuse
    }

    // ---- completion: last finisher scores + resets state for graph replay ----
    if (tid == 0) {
        __threadfence();
        unsigned done = atomicInc(&g_done, NPBLK - 1);   // wraps to 0 itself
        is_last = (done == NPBLK - 1);
    }
    __syncthreads();

    if (is_last) {
        if (tid < NMASKS) {
            unsigned a = *(volatile unsigned*)&g_mA[tid];
            unsigned c = *(volatile unsigned*)&g_mC[tid];
            unsigned p = *(volatile unsigned*)&g_mP[tid];

            float area  = (float)a;
            float conn  = (float)c;
            float perim = (float)p;

            float safe_area  = (area > 0.0f) ? area : 1.0f;
            float area_ratio = area / (float)(W * W);
            float area_score = (area_ratio >= 0.001f && area_ratio <= 0.5f) ? 1.0f : 0.1f;

            float comp_score = (conn > 0.0f)
                ? fminf(1.0f, 10.0f / (conn / safe_area + 1e-6f))
                : 0.1f;

            float par = perim / safe_area;
            float shape_score = (area > 0.0f)
                ? ((par <= 100.0f) ? 1.0f : fmaxf(0.1f, 100.0f / (par + 1e-6f)))
                : 0.1f;

            float validity = 0.4f * area_score + 0.3f * comp_score + 0.3f * shape_score;
            out[tid] = fmaxf(0.05f, validity);

            g_mA[tid] = 0u; g_mC[tid] = 0u; g_mP[tid] = 0u;
        }
        if (tid == 0) g_ticket = 0u;
    }
}

extern "C" void kernel_launch(void* const* d_in, const int* in_sizes, int n_in,
                              void* d_out, int out_size) {
    const float* masks = (const float*)d_in[0];
    float* out = (float*)d_out;
    (void)in_sizes; (void)n_in; (void)out_size;

    prior_kernel<<<NPBLK, 256>>>(masks, out);
}

// round 12
// speedup vs baseline: 1.0326x; 1.0326x over previous
#include <cuda_runtime.h>
#include <cuda_bf16.h>

#define NMASKS 128
#define W      1024
#define TILE_ROWS 62
#define TILES_PER_MASK 17                    // 16 x 62 rows + 1 x 32 rows
#define NTILES (NMASKS * TILES_PER_MASK)     // 2176
#define NPBLK  740                           // 148 SMs x 5 resident blocks
#define HALO_MAX 64                          // 62 + 2
#define STRIDE 35                            // gcd(35,32)=1 -> conflict-free

__device__ unsigned g_mA[NMASKS];            // zero-init; reset by last block
__device__ unsigned g_mC[NMASKS];
__device__ unsigned g_mP[NMASKS];
__device__ unsigned g_ticket = 0;            // reset by last block each launch
__device__ unsigned g_done = 0;              // atomicInc wrap -> self-resetting

__device__ __forceinline__ void csa(unsigned a, unsigned b, unsigned c,
                                    unsigned &s, unsigned &cy) {
    unsigned t = a ^ b;
    s  = t ^ c;
    cy = (a & b) | (t & c);
}

// Pack rows q, q+qstep, ... of tile (mask, tile) into buf (interleaved bitplanes).
// Identical inner body to the proven R5 pack: 8 batched LDG.128, then ballots.
__device__ __forceinline__ void pack_tile(unsigned (*buf)[STRIDE],
                                          const float4* __restrict__ base,
                                          int r0, int halo, int q, int qstep,
                                          int lane) {
    for (int k = q; k < halo; k += qstep) {
        int gr = r0 - 1 + k;
        if ((unsigned)gr >= (unsigned)W) {
            buf[k][lane] = 0u;
        } else {
            const float4* __restrict__ rowp = base + (size_t)gr * (W / 4);
            float4 v[8];
            #pragma unroll
            for (int it = 0; it < 8; it++) v[it] = rowp[it * 32 + lane];
            #pragma unroll
            for (int it = 0; it < 8; it++) {
                unsigned p0 = __ballot_sync(0xffffffffu, v[it].x > 0.0f);
                unsigned p1 = __ballot_sync(0xffffffffu, v[it].y > 0.0f);
                unsigned p2 = __ballot_sync(0xffffffffu, v[it].z > 0.0f);
                unsigned p3 = __ballot_sync(0xffffffffu, v[it].w > 0.0f);
                unsigned mine = (lane == 0) ? p0 : (lane == 1) ? p1
                              : (lane == 2) ? p2 : p3;
                if (lane < 4) buf[k][1 + 4 * it + lane] = mine;
            }
        }
    }
}

// Compute the tile in buf with 128 threads (ctid 0..127); accumulate + REDG.
__device__ __forceinline__ void compute_tile(const unsigned (*buf)[STRIDE],
                                             int rows, int mask, int ctid, int lane) {
    unsigned accA = 0, accC = 0, accP = 0;
    const int ntasks = rows * 8;             // 496 or 256
    #pragma unroll 1
    for (int base_t = 0; base_t < ntasks; base_t += 128) {
        int id = ctid + base_t;
        if (id >= ntasks) break;
        int g = id & 7;
        int r = id >> 3;
        const unsigned* __restrict__ Tr = buf[r];
        const unsigned* __restrict__ Mr = buf[r + 1];
        const unsigned* __restrict__ Br = buf[r + 2];
        int s = 1 + 4 * g;

        unsigned T[4], M[4], B[4];
        #pragma unroll
        for (int k = 0; k < 4; k++) { T[k] = Tr[s+k]; M[k] = Mr[s+k]; B[k] = Br[s+k]; }
        unsigned Tp3 = Tr[s-1], Mp3 = Mr[s-1], Bp3 = Br[s-1];
        unsigned Tn0 = Tr[s+4], Mn0 = Mr[s+4], Bn0 = Br[s+4];

        unsigned TSL = (T[3] << 1) | (Tp3 >> 31), TSR = (T[0] >> 1) | (Tn0 << 31);
        unsigned MSL = (M[3] << 1) | (Mp3 >> 31), MSR = (M[0] >> 1) | (Mn0 << 31);
        unsigned BSL = (B[3] << 1) | (Bp3 >> 31), BSR = (B[0] >> 1) | (Bn0 << 31);

        #pragma unroll
        for (int k = 0; k < 4; k++) {
            unsigned tl = (k > 0) ? T[k-1] : TSL;
            unsigned ml = (k > 0) ? M[k-1] : MSL;
            unsigned bl = (k > 0) ? B[k-1] : BSL;
            unsigned tr = (k < 3) ? T[k+1] : TSR;
            unsigned mr = (k < 3) ? M[k+1] : MSR;
            unsigned br = (k < 3) ? B[k+1] : BSR;
            unsigned tt = T[k], bot = B[k], mid = M[k];

            unsigned s1, c1, s2, c2, s3, c3;
            csa(tl, tt, tr, s1, c1);
            csa(ml, mr, bl, s2, c2);
            csa(bot, br, s1, s3, c3);
            unsigned s4 = s2 ^ s3, c4 = s2 & s3;
            unsigned u1, v1;
            csa(c1, c2, c3, u1, v1);
            unsigned u2 = u1 ^ c4, v2 = u1 & c4;
            unsigned b0 = s4, b1 = u2, b2 = v1 ^ v2, b3 = v1 & v2;

            accA += __popc(mid);

            unsigned conn = __popc(b0 & mid) + 2u * __popc(b1 & mid)
                          + 4u * __popc(b2 & mid) + 8u * __popc(b3 & mid);
            unsigned tot  = __popc(b0) + 2u * __popc(b1)
                          + 4u * __popc(b2) + 8u * __popc(b3);
            unsigned perim = (tot - conn)
                           + 4u * __popc(b3 & mid)
                           + 2u * __popc(b2 & b1 & mid)
                           +      __popc(b2 & b0 & mid);
            accC += conn;
            accP += perim;
        }
    }
    accA = __reduce_add_sync(0xffffffffu, accA);
    accC = __reduce_add_sync(0xffffffffu, accC);
    accP = __reduce_add_sync(0xffffffffu, accP);
    if (lane == 0) {
        atomicAdd(&g_mA[mask], accA);
        atomicAdd(&g_mC[mask], accC);
        atomicAdd(&g_mP[mask], accP);
    }
}

__global__ __launch_bounds__(256, 5)
void prior_kernel(const float* __restrict__ masks, float* __restrict__ out) {
    // Double-buffered interleaved-bitplane tiles; guard slots 0/33/34 stay zero.
    __shared__ unsigned sbuf[2][HALO_MAX][STRIDE];   // 18.5 KB
    __shared__ int sT[2];
    __shared__ int is_last;

    const int tid  = threadIdx.x;
    const int lane = tid & 31;
    const int wp   = tid >> 5;               // 8 warps
    const int q    = wp & 3;                 // index within role group
    const int grpB = wp >> 2;                // 0: warps 0-3, 1: warps 4-7
    const int ctid = q * 32 + lane;          // compute-thread id 0..127

    for (int j = tid; j < 2 * HALO_MAX; j += 256) {
        unsigned (*b)[STRIDE] = sbuf[j >= HALO_MAX];
        int r = (j >= HALO_MAX) ? j - HALO_MAX : j;
        b[r][0] = 0u; b[r][33] = 0u; b[r][34] = 0u;
    }

    // ---- prologue: ticket 0, pack with ALL 8 warps; prefetch ticket 1 ----
    if (tid == 0) sT[0] = (int)atomicAdd(&g_ticket, 1u);
    __syncthreads();
    int cur = sT[0];
    if (cur < NTILES) {
        int m  = cur / TILES_PER_MASK;
        int ti = cur - m * TILES_PER_MASK;
        int r0 = ti * TILE_ROWS;
        int halo = ((ti < 16) ? TILE_ROWS : (W - 16 * TILE_ROWS)) + 2;
        const float4* base = (const float4*)(masks + (size_t)m * (size_t)(W * W));
        pack_tile(sbuf[0], base, r0, halo, wp, 8, lane);
    }
    if (tid == 0) sT[1] = (int)atomicAdd(&g_ticket, 1u);
    __syncthreads();

    // ---- steady state: 4 warps pack next tile, 4 warps compute current ----
    int p = 0, iter = 0;
    while (cur < NTILES) {
        const int nxt = sT[p ^ 1];
        const bool packer = (grpB ^ (iter & 1)) != 0;   // roles alternate per tile

        if (packer) {
            if (nxt < NTILES) {
                int m  = nxt / TILES_PER_MASK;
                int ti = nxt - m * TILES_PER_MASK;
                int r0 = ti * TILE_ROWS;
                int halo = ((ti < 16) ? TILE_ROWS : (W - 16 * TILE_ROWS)) + 2;
                const float4* base =
                    (const float4*)(masks + (size_t)m * (size_t)(W * W));
                pack_tile(sbuf[p ^ 1], base, r0, halo, q, 4, lane);
            }
        } else {
            int m  = cur / TILES_PER_MASK;
            int ti = cur - m * TILES_PER_MASK;
            int rows = (ti < 16) ? TILE_ROWS : (W - 16 * TILE_ROWS);
            compute_tile(sbuf[p], rows, m, ctid, lane);
        }

        if (tid == 0) sT[p] = (int)atomicAdd(&g_ticket, 1u);  // ticket for tile after nxt
        __syncthreads();    // publishes sbuf[p^1], sT[p]; guards buffer reuse

        cur = nxt;
        p ^= 1;
        iter++;
    }

    // ---- completion: last finisher scores + resets state for graph replay ----
    if (tid == 0) {
        __threadfence();
        unsigned done = atomicInc(&g_done, NPBLK - 1);   // wraps to 0 itself
        is_last = (done == NPBLK - 1);
    }
    __syncthreads();

    if (is_last) {
        if (tid < NMASKS) {
            unsigned a = *(volatile unsigned*)&g_mA[tid];
            unsigned c = *(volatile unsigned*)&g_mC[tid];
            unsigned pm = *(volatile unsigned*)&g_mP[tid];

            float area  = (float)a;
            float conn  = (float)c;
            float perim = (float)pm;

            float safe_area  = (area > 0.0f) ? area : 1.0f;
            float area_ratio = area / (float)(W * W);
            float area_score = (area_ratio >= 0.001f && area_ratio <= 0.5f) ? 1.0f : 0.1f;

            float comp_score = (conn > 0.0f)
                ? fminf(1.0f, 10.0f / (conn / safe_area + 1e-6f))
                : 0.1f;

            float par = perim / safe_area;
            float shape_score = (area > 0.0f)
                ? ((par <= 100.0f) ? 1.0f : fmaxf(0.1f, 100.0f / (par + 1e-6f)))
                : 0.1f;

            float validity = 0.4f * area_score + 0.3f * comp_score + 0.3f * shape_score;
            out[tid] = fmaxf(0.05f, validity);

            g_mA[tid] = 0u; g_mC[tid] = 0u; g_mP[tid] = 0u;
        }
        if (tid == 0) g_ticket = 0u;
    }
}

extern "C" void kernel_launch(void* const* d_in, const int* in_sizes, int n_in,
                              void* d_out, int out_size) {
    const float* masks = (const float*)d_in[0];
    float* out = (float*)d_out;
    (void)in_sizes; (void)n_in; (void)out_size;

    prior_kernel<<<NPBLK, 256>>>(masks, out);
}

// round 13
// speedup vs baseline: 1.1226x; 1.0872x over previous
#include <cuda_runtime.h>
#include <cuda_bf16.h>

#define NMASKS 128
#define W      1024
#define TILE_ROWS 62
#define TILES_PER_MASK 17                    // 16 x 62 rows + 1 x 32 rows
#define NTILES (NMASKS * TILES_PER_MASK)     // 2176
#define NPBLK  740                           // 148 SMs x 5 resident blocks
#define HALO_MAX 64                          // 62 + 2 -> 8 pack iters/warp
#define STRIDE 35                            // gcd(35,32)=1 -> conflict-free
#define STAGGER_CYC 9000                     // ~ one compute-phase, in SM cycles

__device__ unsigned g_mA[NMASKS];            // zero-init; reset by last block
__device__ unsigned g_mC[NMASKS];
__device__ unsigned g_mP[NMASKS];
__device__ unsigned g_ticket = 0;            // reset by last block each launch
__device__ unsigned g_done = 0;              // atomicInc wrap -> self-resetting

__device__ __forceinline__ void csa(unsigned a, unsigned b, unsigned c,
                                    unsigned &s, unsigned &cy) {
    unsigned t = a ^ b;
    s  = t ^ c;
    cy = (a & b) | (t & c);
}

__global__ __launch_bounds__(256, 5)
void prior_kernel(const float* __restrict__ masks, float* __restrict__ out) {
    // Interleaved-bitplane packed rows. Group g (128 cols) occupies slots
    // 1+4g..4+4g. Guard slots 0 / 33 / 34 stay zero.
    __shared__ unsigned srows[HALO_MAX][STRIDE];
    __shared__ unsigned red[8][3];
    __shared__ int cur_tile;
    __shared__ int is_last;

    const int tid  = threadIdx.x;
    const int lane = tid & 31;
    const int wp   = tid >> 5;               // 8 warps

    for (int j = tid; j < HALO_MAX; j += 256) {
        srows[j][0] = 0u; srows[j][33] = 0u; srows[j][34] = 0u;
    }

    // ---- phase stagger: co-resident blocks (bid, bid+148, ... -> distinct
    // bid%5 since 148=3 mod 5 generates Z5) offset their pack/compute phases
    // so compute windows no longer coincide and DRAM never drains. Dynamic
    // tickets absorb the skew (late starters just take fewer tiles).
    {
        unsigned r = blockIdx.x % 5u;
        if (r != 0u) {
            long long tgt = clock64() + (long long)r * STAGGER_CYC;
            while (clock64() < tgt) { }
        }
    }

    // ---- persistent loop: dynamic tile tickets ----
    while (true) {
        if (tid == 0) cur_tile = (int)atomicAdd(&g_ticket, 1u);
        __syncthreads();                     // publishes cur_tile; guards smem reuse
        const int t = cur_tile;
        if (t >= NTILES) break;

        const int mask = t / TILES_PER_MASK;
        const int tile = t - mask * TILES_PER_MASK;
        const int r0   = tile * TILE_ROWS;
        const int rows = (tile < 16) ? TILE_ROWS : (W - 16 * TILE_ROWS); // 62|32
        const int halo = rows + 2;
        const float4* __restrict__ base =
            (const float4*)(masks + (size_t)mask * (size_t)(W * W));

        // ---- pack: batched float4 loads (8 LDG.128 in flight), then ballots ----
        for (int k = wp; k < halo; k += 8) {
            int gr = r0 - 1 + k;
            if ((unsigned)gr >= (unsigned)W) {
                srows[k][lane] = 0u;
            } else {
                const float4* __restrict__ rowp = base + (size_t)gr * (W / 4);
                float4 v[8];
                #pragma unroll
                for (int it = 0; it < 8; it++) v[it] = rowp[it * 32 + lane];
                #pragma unroll
                for (int it = 0; it < 8; it++) {
                    unsigned p0 = __ballot_sync(0xffffffffu, v[it].x > 0.0f);
                    unsigned p1 = __ballot_sync(0xffffffffu, v[it].y > 0.0f);
                    unsigned p2 = __ballot_sync(0xffffffffu, v[it].z > 0.0f);
                    unsigned p3 = __ballot_sync(0xffffffffu, v[it].w > 0.0f);
                    unsigned mine = (lane == 0) ? p0 : (lane == 1) ? p1
                                  : (lane == 2) ? p2 : p3;
                    if (lane < 4) srows[k][1 + 4 * it + lane] = mine;
                }
            }
        }
        __syncthreads();

        // ---- compute: rows x 8 groups tasks over 256 threads ----
        unsigned accA = 0, accC = 0, accP = 0;
        const int ntasks = rows * 8;         // 496 or 256
        #pragma unroll 1
        for (int base_t = 0; base_t < ntasks; base_t += 256) {
            int id = tid + base_t;
            if (id >= ntasks) break;
            int g  = id & 7;
            int r  = id >> 3;
            const unsigned* __restrict__ Tr = srows[r];
            const unsigned* __restrict__ Mr = srows[r + 1];
            const unsigned* __restrict__ Br = srows[r + 2];
            int s = 1 + 4 * g;

            unsigned T[4], M[4], B[4];
            #pragma unroll
            for (int k = 0; k < 4; k++) { T[k] = Tr[s+k]; M[k] = Mr[s+k]; B[k] = Br[s+k]; }
            unsigned Tp3 = Tr[s-1], Mp3 = Mr[s-1], Bp3 = Br[s-1];
            unsigned Tn0 = Tr[s+4], Mn0 = Mr[s+4], Bn0 = Br[s+4];

            unsigned TSL = (T[3] << 1) | (Tp3 >> 31), TSR = (T[0] >> 1) | (Tn0 << 31);
            unsigned MSL = (M[3] << 1) | (Mp3 >> 31), MSR = (M[0] >> 1) | (Mn0 << 31);
            unsigned BSL = (B[3] << 1) | (Bp3 >> 31), BSR = (B[0] >> 1) | (Bn0 << 31);

            #pragma unroll
            for (int k = 0; k < 4; k++) {
                unsigned tl = (k > 0) ? T[k-1] : TSL;
                unsigned ml = (k > 0) ? M[k-1] : MSL;
                unsigned bl = (k > 0) ? B[k-1] : BSL;
                unsigned tr = (k < 3) ? T[k+1] : TSR;
                unsigned mr = (k < 3) ? M[k+1] : MSR;
                unsigned br = (k < 3) ? B[k+1] : BSR;
                unsigned tt = T[k], bot = B[k], mid = M[k];

                unsigned s1, c1, s2, c2, s3, c3;
                csa(tl, tt, tr, s1, c1);
                csa(ml, mr, bl, s2, c2);
                csa(bot, br, s1, s3, c3);
                unsigned s4 = s2 ^ s3, c4 = s2 & s3;
                unsigned u1, v1;
                csa(c1, c2, c3, u1, v1);
                unsigned u2 = u1 ^ c4, v2 = u1 & c4;
                unsigned b0 = s4, b1 = u2, b2 = v1 ^ v2, b3 = v1 & v2;

                accA += __popc(mid);

                unsigned conn = __popc(b0 & mid) + 2u * __popc(b1 & mid)
                              + 4u * __popc(b2 & mid) + 8u * __popc(b3 & mid);
                unsigned tot  = __popc(b0) + 2u * __popc(b1)
                              + 4u * __popc(b2) + 8u * __popc(b3);
                unsigned perim = (tot - conn)
                               + 4u * __popc(b3 & mid)
                               + 2u * __popc(b2 & b1 & mid)
                               +      __popc(b2 & b0 & mid);

                accC += conn;
                accP += perim;
            }
        }

        // ---- per-tile block reduction -> per-mask atomic accumulation ----
        accA = __reduce_add_sync(0xffffffffu, accA);
        accC = __reduce_add_sync(0xffffffffu, accC);
        accP = __reduce_add_sync(0xffffffffu, accP);
        if (lane == 0) { red[wp][0] = accA; red[wp][1] = accC; red[wp][2] = accP; }
        __syncthreads();
        if (tid == 0) {
            unsigned a = 0, c = 0, p = 0;
            #pragma unroll
            for (int w2 = 0; w2 < 8; w2++) { a += red[w2][0]; c += red[w2][1]; p += red[w2][2]; }
            atomicAdd(&g_mA[mask], a);
            atomicAdd(&g_mC[mask], c);
            atomicAdd(&g_mP[mask], p);
        }
        // loop-top __syncthreads() protects srows before next tile
    }

    // ---- completion: last finisher scores + resets state for graph replay ----
    if (tid == 0) {
        __threadfence();
        unsigned done = atomicInc(&g_done, NPBLK - 1);   // wraps to 0 itself
        is_last = (done == NPBLK - 1);
    }
    __syncthreads();

    if (is_last) {
        if (tid < NMASKS) {
            unsigned a = *(volatile unsigned*)&g_mA[tid];
            unsigned c = *(volatile unsigned*)&g_mC[tid];
            unsigned p = *(volatile unsigned*)&g_mP[tid];

            float area  = (float)a;
            float conn  = (float)c;
            float perim = (float)p;

            float safe_area  = (area > 0.0f) ? area : 1.0f;
            float area_ratio = area / (float)(W * W);
            float area_score = (area_ratio >= 0.001f && area_ratio <= 0.5f) ? 1.0f : 0.1f;

            float comp_score = (conn > 0.0f)
                ? fminf(1.0f, 10.0f / (conn / safe_area + 1e-6f))
                : 0.1f;

            float par = perim / safe_area;
            float shape_score = (area > 0.0f)
                ? ((par <= 100.0f) ? 1.0f : fmaxf(0.1f, 100.0f / (par + 1e-6f)))
                : 0.1f;

            float validity = 0.4f * area_score + 0.3f * comp_score + 0.3f * shape_score;
            out[tid] = fmaxf(0.05f, validity);

            g_mA[tid] = 0u; g_mC[tid] = 0u; g_mP[tid] = 0u;
        }
        if (tid == 0) g_ticket = 0u;
    }
}

extern "C" void kernel_launch(void* const* d_in, const int* in_sizes, int n_in,
                              void* d_out, int out_size) {
    const float* masks = (const float*)d_in[0];
    float* out = (float*)d_out;
    (void)in_sizes; (void)n_in; (void)out_size;

    prior_kernel<<<NPBLK, 256>>>(masks, out);
}